// round 15
// baseline (speedup 1.0000x reference)
#include <cuda_runtime.h>
#include <cuda_bf16.h>

// Retrace: per-(b,d) reverse affine scan + MSE reduction.
// Shapes: B=2048, T=512, D=16. fp32. Output: 1 fp32 scalar.
// Segment-parallel: q_t = gc_t*q_{t+1} + base_t is affine in the carry; each
// segment yields (P,S) with q = P*x + S and MSE quadratic in carry-in x.
// R13: R9 inner loop, but each warp covers 2 sub-segments of 16 steps
// (lanes 0-15 = d at segment 2w, lanes 16-31 = d at segment 2w+1), so a
// block = one b-row (16 chains) x 32 segments. Grid 2048 -> block duration
// halves -> drain-tail idle ~14% -> ~7%. Final reduction via per-block
// partials + self-resetting ticket (no memset node, no atomics contention).

#define RB 2048
#define RT 512
#define RD 16
#define NSEG 32
#define SEGLEN 16
#define BLK 512
#define GAMMA 0.99f

__device__ float        g_part[RB];     // one partial per block (written every run)
__device__ unsigned int g_ticket;       // zero-init; self-resets each run

__global__ __launch_bounds__(BLK, 2)
void retrace_seg_kernel(const float* __restrict__ Q,
                        const float* __restrict__ eQ,
                        const float* __restrict__ tQ,
                        const float* __restrict__ rw,
                        const float* __restrict__ tpp,
                        const float* __restrict__ bpp,
                        float* __restrict__ out)
{
    const int tid  = threadIdx.x;
    const int lane = tid & 31;
    const int w    = tid >> 5;               // warp 0..15
    const int d    = lane & 15;              // chain within row (D=16)
    const int sub  = lane >> 4;              // 0 or 1
    const int seg  = w * 2 + sub;            // time segment 0..31
    const int b    = blockIdx.x;             // block = one b-row

    const size_t base = (size_t)b * (RT * RD) + d;
    const float* q_p   = Q   + base;
    const float* e_p   = eQ  + base;
    const float* tq_p  = tQ  + base;
    const float* r_p   = rw  + base;
    const float* tpp_p = tpp + base;
    const float* bpp_p = bpp + (size_t)b * RT;

    const int lo = seg * SEGLEN;
    int hi = lo + SEGLEN - 1;
    if (hi > RT - 2) hi = RT - 2;            // seg 31: t = 496..510 (15 steps)

    // Backward scan within segment: q = P*x + S (x = carry entering at hi+1)
    float P = 1.0f, S = 0.0f;
    float sumD2 = 0.0f, sumDP = 0.0f, sumP2 = 0.0f;

    #pragma unroll 4
    for (int t = hi; t >= lo; --t) {
        const int j = t + 1;
        float lw  = tpp_p[j * RD] - bpp_p[j];
        float gc  = GAMMA * __expf(fminf(lw, 0.0f));
        float bse = fmaf(GAMMA, e_p[j * RD], r_p[t * RD]);
        bse       = fmaf(-gc, tq_p[j * RD], bse);
        P = gc * P;
        S = fmaf(gc, S, bse);
        float dv = q_p[t * RD] - S;          // diff = dv - P*x
        sumD2 = fmaf(dv, dv, sumD2);
        sumDP = fmaf(dv, P,  sumDP);
        sumP2 = fmaf(P,  P,  sumP2);
    }

    __shared__ float shA [NSEG][RD];
    __shared__ float shB [NSEG][RD];
    __shared__ float shD2[NSEG][RD];
    __shared__ float shDP[NSEG][RD];
    __shared__ float shP2[NSEG][RD];
    shA [seg][d] = P;
    shB [seg][d] = S;
    shD2[seg][d] = sumD2;
    shDP[seg][d] = sumDP;
    shP2[seg][d] = sumP2;
    __syncthreads();

    // Lanes 0-15 of warp 0: serial combine over 32 segments per chain.
    __shared__ float s_partial;
    if (tid < 16) {
        float x = tq_p[(size_t)(RT - 1) * RD];   // carry init = target_Q[b, -1, d]
        float acc = 0.0f;
        #pragma unroll
        for (int s = NSEG - 1; s >= 0; --s) {
            float a2 = shD2[s][d], dp = shDP[s][d], p2 = shP2[s][d];
            acc += fmaf(x, fmaf(x, p2, -2.0f * dp), a2);
            x = fmaf(shA[s][d], x, shB[s][d]);
        }
        const float inv_n = 1.0f / (float)((size_t)RB * (RT - 1) * RD);
        acc *= inv_n;

        #pragma unroll
        for (int off = 8; off > 0; off >>= 1)
            acc += __shfl_down_sync(0x0000FFFFu, acc, off);
        if (tid == 0) {
            g_part[b] = acc;
            s_partial = acc;                 // (unused; keeps store ordering simple)
        }
    }

    // Last-block-done: reduce all partials and write the scalar.
    __shared__ bool s_last;
    __threadfence();
    __syncthreads();
    if (tid == 0) {
        unsigned int t = atomicAdd(&g_ticket, 1u);
        s_last = (t == gridDim.x - 1);
    }
    __syncthreads();
    if (s_last) {
        // 2048 partials, 512 threads -> 4 each
        float v = g_part[tid] + g_part[tid + 512] +
                  g_part[tid + 1024] + g_part[tid + 1536];
        #pragma unroll
        for (int off = 16; off > 0; off >>= 1)
            v += __shfl_down_sync(0xFFFFFFFFu, v, off);
        __shared__ float wsum[16];
        if (lane == 0) wsum[w] = v;
        __syncthreads();
        if (w == 0) {
            float x = (lane < 16) ? wsum[lane] : 0.0f;
            #pragma unroll
            for (int off = 8; off > 0; off >>= 1)
                x += __shfl_down_sync(0xFFFFFFFFu, x, off);
            if (lane == 0) {
                out[0] = x;
                g_ticket = 0;                // self-reset for next launch/replay
            }
        }
    }
}

extern "C" void kernel_launch(void* const* d_in, const int* in_sizes, int n_in,
                              void* d_out, int out_size)
{
    const float* Q   = (const float*)d_in[0];
    const float* eQ  = (const float*)d_in[1];
    const float* tQ  = (const float*)d_in[2];
    const float* rw  = (const float*)d_in[3];
    const float* tpp = (const float*)d_in[4];
    const float* bpp = (const float*)d_in[5];
    float* out = (float*)d_out;

    retrace_seg_kernel<<<RB, BLK>>>(Q, eQ, tQ, rw, tpp, bpp, out);
}

// round 16
// speedup vs baseline: 1.1282x; 1.1282x over previous
#include <cuda_runtime.h>
#include <cuda_bf16.h>

// Retrace: per-(b,d) reverse affine scan + MSE reduction.
// Shapes: B=2048, T=512, D=16. All inputs fp32. Output: 1 fp32 scalar.
// Segment-parallel: q_t = gc_t * q_{t+1} + base_t is affine in the carry, so
// each segment reduces to (P, S) with q = P*x + S, and its squared-error
// contribution is quadratic in x: sumD2 - 2x*sumDP + x^2*sumP2.
// R15: hot loop byte-identical to the 59.4us R9 kernel (512 thr, 16 segments
// x 32 steps, 32 chains/block, grid 1024, scalar LDG, unroll 4). Overhead
// surgery only: no memset node + no d_out atomics -- per-block partials in a
// __device__ array, last-block ticket reduces and stores the scalar.

#define RB 2048
#define RT 512
#define RD 16
#define NSEG 16
#define SEGLEN 32
#define CHAINS_PER_BLK 32
#define NBLK ((RB * RD) / CHAINS_PER_BLK)   // 1024
#define GAMMA 0.99f

__device__ float        g_part[NBLK];    // per-block partials (overwritten each run)
__device__ unsigned int g_ticket;        // zero-init; self-resets each run

__global__ __launch_bounds__(512, 2)
void retrace_seg_kernel(const float* __restrict__ Q,
                        const float* __restrict__ eQ,
                        const float* __restrict__ tQ,
                        const float* __restrict__ rw,
                        const float* __restrict__ tpp,
                        const float* __restrict__ bpp,
                        float* __restrict__ out)
{
    const int lane = threadIdx.x & 31;       // chain within block
    const int seg  = threadIdx.x >> 5;       // time segment 0..15
    const int chain = blockIdx.x * CHAINS_PER_BLK + lane;  // 0 .. B*D-1
    const int b = chain >> 4;                // D = 16
    const int d = chain & 15;

    const size_t base = (size_t)b * (RT * RD) + d;
    const float* q_p   = Q   + base;
    const float* e_p   = eQ  + base;
    const float* tq_p  = tQ  + base;
    const float* r_p   = rw  + base;
    const float* tpp_p = tpp + base;
    const float* bpp_p = bpp + (size_t)b * RT;

    const int lo = seg * SEGLEN;
    const int hi = (seg == NSEG - 1) ? (RT - 2) : (lo + SEGLEN - 1);

    // hoist carry load (used only by warp 0 after the barrier)
    float x0 = 0.0f;
    if (seg == 0)
        x0 = tq_p[(size_t)(RT - 1) * RD];    // initial carry = target_Q[:, -1]

    // Backward scan within segment: q = P*x + S (x = carry entering at t=hi+1)
    float P = 1.0f, S = 0.0f;
    float sumD2 = 0.0f, sumDP = 0.0f, sumP2 = 0.0f;

    #pragma unroll 4
    for (int t = hi; t >= lo; --t) {
        const int j = t + 1;
        float lw  = tpp_p[j * RD] - bpp_p[j];
        float gc  = GAMMA * __expf(fminf(lw, 0.0f));
        float bse = fmaf(GAMMA, e_p[j * RD], r_p[t * RD]);
        bse       = fmaf(-gc, tq_p[j * RD], bse);
        P = gc * P;
        S = fmaf(gc, S, bse);
        float dv = q_p[t * RD] - S;          // diff = dv - P*x
        sumD2 = fmaf(dv, dv, sumD2);
        sumDP = fmaf(dv, P,  sumDP);
        sumP2 = fmaf(P,  P,  sumP2);
    }

    __shared__ float shA [NSEG][CHAINS_PER_BLK];
    __shared__ float shB [NSEG][CHAINS_PER_BLK];
    __shared__ float shD2[NSEG][CHAINS_PER_BLK];
    __shared__ float shDP[NSEG][CHAINS_PER_BLK];
    __shared__ float shP2[NSEG][CHAINS_PER_BLK];
    shA [seg][lane] = P;
    shB [seg][lane] = S;
    shD2[seg][lane] = sumD2;
    shDP[seg][lane] = sumDP;
    shP2[seg][lane] = sumP2;
    __syncthreads();

    // Warp 0: serial combine over 16 segments for each of the 32 chains.
    if (seg == 0) {
        float x = x0;
        float acc = 0.0f;
        #pragma unroll
        for (int s = NSEG - 1; s >= 0; --s) {
            float a2 = shD2[s][lane], dp = shDP[s][lane], p2 = shP2[s][lane];
            acc += fmaf(x, fmaf(x, p2, -2.0f * dp), a2);
            x = fmaf(shA[s][lane], x, shB[s][lane]);
        }
        const float inv_n = 1.0f / (float)((size_t)RB * (RT - 1) * RD);
        acc *= inv_n;

        #pragma unroll
        for (int off = 16; off > 0; off >>= 1)
            acc += __shfl_down_sync(0xFFFFFFFFu, acc, off);
        if (lane == 0)
            g_part[blockIdx.x] = acc;
    }

    // Last-block-done: reduce all partials and write the scalar (no memset,
    // no atomics on d_out). Ticket self-resets so graph replays are correct.
    __shared__ bool s_last;
    __threadfence();
    __syncthreads();
    if (threadIdx.x == 0) {
        unsigned int t = atomicAdd(&g_ticket, 1u);
        s_last = (t == gridDim.x - 1);
    }
    __syncthreads();
    if (s_last) {
        const int tid = threadIdx.x;
        float v = g_part[tid] + g_part[tid + 512];   // 1024 partials, 512 thr
        #pragma unroll
        for (int off = 16; off > 0; off >>= 1)
            v += __shfl_down_sync(0xFFFFFFFFu, v, off);
        __shared__ float wsum[16];
        const int w = tid >> 5;
        if (lane == 0) wsum[w] = v;
        __syncthreads();
        if (w == 0) {
            float z = (lane < 16) ? wsum[lane] : 0.0f;
            #pragma unroll
            for (int off = 8; off > 0; off >>= 1)
                z += __shfl_down_sync(0xFFFFFFFFu, z, off);
            if (lane == 0) {
                out[0] = z;
                g_ticket = 0;                // self-reset for next launch/replay
            }
        }
    }
}

extern "C" void kernel_launch(void* const* d_in, const int* in_sizes, int n_in,
                              void* d_out, int out_size)
{
    const float* Q   = (const float*)d_in[0];
    const float* eQ  = (const float*)d_in[1];
    const float* tQ  = (const float*)d_in[2];
    const float* rw  = (const float*)d_in[3];
    const float* tpp = (const float*)d_in[4];
    const float* bpp = (const float*)d_in[5];
    float* out = (float*)d_out;

    retrace_seg_kernel<<<NBLK, NSEG * 32>>>(Q, eQ, tQ, rw, tpp, bpp, out);
}